// round 14
// baseline (speedup 1.0000x reference)
#include <cuda_runtime.h>
#include <cuda_fp16.h>
#include <math.h>
#include <stdint.h>

// ---------------- problem constants ----------------
#define N_NODES   65536
#define IN_DIM    512
#define OUT_DIM   512
#define N_EDGES   524288
#define K_TOTAL   (2 * IN_DIM)   // 1024
#define BN_EPS    1e-5f
#define NORM_EPS  1e-6f

// ---------------- device scratch ----------------
__device__ int    g_is64;
__device__ int    g_deg[N_NODES];
__device__ int    g_incl[N_NODES];
__device__ int    g_excl[N_NODES];
__device__ int    g_cursor[N_NODES];
__device__ int    g_blockSums[64];
__device__ int    g_tgtSorted[N_EDGES];
// X = concat(feat, agg) quantized to fp16: [node][1024] half
__device__ uint4  g_Xh[(size_t)N_NODES * K_TOTAL * 2 / 16];    // 128 MB
// W quantized to fp16: [512][1024] half
__device__ uint4  g_Wh[(size_t)OUT_DIM * K_TOTAL * 2 / 16];    // 1 MB
// pre-normalization activations, fp16: [node][512] half
__device__ uint4  g_yh[(size_t)N_NODES * OUT_DIM * 2 / 16];    // 64 MB

// ---------------- helpers ----------------
__device__ __forceinline__ uint32_t smem_u32(const void* p) {
    uint32_t a;
    asm("{ .reg .u64 t; cvta.to.shared.u64 t, %1; cvt.u32.u64 %0, t; }" : "=r"(a) : "l"(p));
    return a;
}
__device__ __forceinline__ uint2 quant4_h(float4 v) {
    __half2 p0, p1;
    p0.x = __float2half_rn(v.x); p0.y = __float2half_rn(v.y);
    p1.x = __float2half_rn(v.z); p1.y = __float2half_rn(v.w);
    return make_uint2(*(uint32_t*)&p0, *(uint32_t*)&p1);
}
__device__ __forceinline__ uint32_t pack_h2(float a, float b) {
    __half2 p;
    p.x = __float2half_rn(a); p.y = __float2half_rn(b);
    return *(uint32_t*)&p;
}
__device__ __forceinline__ void ldsm4(uint32_t* r, uint32_t addr) {
    asm volatile("ldmatrix.sync.aligned.m8n8.x4.shared.b16 {%0,%1,%2,%3}, [%4];"
                 : "=r"(r[0]), "=r"(r[1]), "=r"(r[2]), "=r"(r[3]) : "r"(addr));
}
__device__ __forceinline__ void mma_f16(float* d, const uint32_t* a, const uint32_t* b) {
    asm volatile("mma.sync.aligned.m16n8k16.row.col.f32.f16.f16.f32 "
                 "{%0,%1,%2,%3}, {%4,%5,%6,%7}, {%8,%9}, {%0,%1,%2,%3};"
                 : "+f"(d[0]), "+f"(d[1]), "+f"(d[2]), "+f"(d[3])
                 : "r"(a[0]), "r"(a[1]), "r"(a[2]), "r"(a[3]), "r"(b[0]), "r"(b[1]));
}
__device__ __forceinline__ void cp16(uint32_t dst, const void* src) {
    asm volatile("cp.async.cg.shared.global [%0], [%1], 16;" :: "r"(dst), "l"(src));
}

// ---------------- edge index dtype ----------------
__device__ __forceinline__ int load_edge(const void* ei, int idx) {
    if (g_is64) return (int)((const long long*)ei)[idx];
    return ((const int*)ei)[idx];
}

// ---------------- CSR build ----------------
__global__ void k_zero_deg(const int* __restrict__ ei32) {
    int i = blockIdx.x * blockDim.x + threadIdx.x;
    if (i < N_NODES) g_deg[i] = 0;
    if (i == 0) {
        int allzero = 1;
        for (int j = 0; j < 64; j++)
            if (ei32[2 * j + 1] != 0) { allzero = 0; break; }
        g_is64 = allzero;
    }
}
__global__ void k_hist(const void* __restrict__ ei) {
    int e = blockIdx.x * blockDim.x + threadIdx.x;
    if (e < N_EDGES) atomicAdd(&g_deg[load_edge(ei, e)], 1);
}
__global__ void k_scan_block() {
    __shared__ int s[1024];
    int t = threadIdx.x, gid = blockIdx.x * 1024 + t;
    s[t] = g_deg[gid];
    __syncthreads();
    #pragma unroll
    for (int off = 1; off < 1024; off <<= 1) {
        int v = (t >= off) ? s[t - off] : 0;
        __syncthreads();
        s[t] += v;
        __syncthreads();
    }
    g_incl[gid] = s[t];
    if (t == 1023) g_blockSums[blockIdx.x] = s[t];
}
// fused: per-block inline prefix of blockSums + finish (replaces scan_sums)
__global__ void k_scan_finish() {
    __shared__ int bsum[64];
    int t = threadIdx.x;
    if (t < 64) bsum[t] = g_blockSums[t];
    __syncthreads();
    int prefix = 0;
    #pragma unroll
    for (int j = 0; j < 64; j++)
        prefix += (j < blockIdx.x) ? bsum[j] : 0;
    int gid = blockIdx.x * 1024 + t;
    int excl = g_incl[gid] - g_deg[gid] + prefix;
    g_excl[gid] = excl;
    g_cursor[gid] = excl;
}
__global__ void k_scatter_edges(const void* __restrict__ ei) {
    int e = blockIdx.x * blockDim.x + threadIdx.x;
    if (e < N_EDGES) {
        int src = load_edge(ei, e);
        int tgt = load_edge(ei, N_EDGES + e);
        g_tgtSorted[atomicAdd(&g_cursor[src], 1)] = tgt;
    }
}

// ---------------- feat half of X -> fp16 ----------------
__global__ void k_quantF(const float* __restrict__ feat) {
    int idx = blockIdx.x * blockDim.x + threadIdx.x;   // one float4 each
    if (idx >= N_NODES * IN_DIM / 4) return;
    int node = idx >> 7;
    int c4   = idx & 127;
    float4 v = ((const float4*)feat)[idx];
    ((uint2*)g_Xh)[(size_t)node * 256 + c4] = quant4_h(v);
}

// ---------------- gather aggregation (fp16 source) -> fp16 agg half ------
__global__ void k_aggregate() {
    int node = blockIdx.x, t = threadIdx.x;     // 0..127, one uint2 (4 halves)
    int start = g_excl[node];
    int end   = start + g_deg[node];
    const uint2* xh = (const uint2*)g_Xh;
    float4 acc = make_float4(0.f, 0.f, 0.f, 0.f);
    int e = start;
    for (; e + 1 < end; e += 2) {
        int t0 = g_tgtSorted[e];
        int t1 = g_tgtSorted[e + 1];
        uint2 v0 = __ldg(&xh[(size_t)t0 * 256 + t]);
        uint2 v1 = __ldg(&xh[(size_t)t1 * 256 + t]);
        float2 a0 = __half22float2(*(__half2*)&v0.x);
        float2 a1 = __half22float2(*(__half2*)&v0.y);
        float2 b0 = __half22float2(*(__half2*)&v1.x);
        float2 b1 = __half22float2(*(__half2*)&v1.y);
        acc.x += a0.x + b0.x; acc.y += a0.y + b0.y;
        acc.z += a1.x + b1.x; acc.w += a1.y + b1.y;
    }
    if (e < end) {
        int t0 = g_tgtSorted[e];
        uint2 v0 = __ldg(&xh[(size_t)t0 * 256 + t]);
        float2 a0 = __half22float2(*(__half2*)&v0.x);
        float2 a1 = __half22float2(*(__half2*)&v0.y);
        acc.x += a0.x; acc.y += a0.y; acc.z += a1.x; acc.w += a1.y;
    }
    ((uint2*)g_Xh)[(size_t)node * 256 + 128 + t] = quant4_h(acc);
}

// ---------------- quantize W to fp16 ----------------
__global__ void k_quantW(const float* __restrict__ W) {
    int idx = blockIdx.x * blockDim.x + threadIdx.x;
    if (idx >= OUT_DIM * K_TOTAL / 4) return;
    float4 v = ((const float4*)W)[idx];
    ((uint2*)g_Wh)[idx] = quant4_h(v);
}

// ---------------- fp16 mma.sync GEMM: CTA 128(M) x 256(N), BK=32 ---------
// 512 threads, 16 warps; 3-stage cp.async pipeline, ONE barrier per K-iter:
//   wait_group(1); __syncthreads(); issue(s+2); compute(s%3);
#define ROW_B   80                          // smem row stride bytes (32 fp16 + pad)
#define A_ST    (128 * ROW_B)               // 10240
#define B_ST    (256 * ROW_B)               // 20480
#define SM_PAR  0
#define SM_A    4096                        // 3 buf x A_ST
#define SM_B    (SM_A + 3 * A_ST)           // 34816; 3 buf x B_ST
#define SMEM_BYTES (SM_B + 3 * B_ST)        // 96256

__global__ void __launch_bounds__(512)
k_gemm_mma(const float* __restrict__ bias,
           const float* __restrict__ gamma,
           const float* __restrict__ beta,
           const float* __restrict__ rmean,
           const float* __restrict__ rvar)
{
    extern __shared__ char smem[];
    uint32_t sb = smem_u32(smem);
    int tid  = threadIdx.x;
    int wid  = tid >> 5;
    int lane = tid & 31;
    int warp_m = wid & 3;
    int warp_n = wid >> 2;
    int bm = blockIdx.y * 128;
    int bn = blockIdx.x * 256;

    if (tid < 256) {
        int n = bn + tid;
        float s = gamma[n] * rsqrtf(rvar[n] + BN_EPS);
        ((float*)(smem + SM_PAR))[tid]       = bias[n];
        ((float*)(smem + SM_PAR))[256 + tid] = s;
        ((float*)(smem + SM_PAR))[512 + tid] = beta[n] - rmean[n] * s;
    }

    const char* xh = (const char*)g_Xh;
    const char* wh = (const char*)g_Wh;

    auto issue = [&](int s, int b) {
        int k0 = s * 32;
        {
            int r = tid >> 2;
            int c = tid & 3;
            const char* src = xh + ((size_t)(bm + r) * K_TOTAL + k0 + c * 8) * 2;
            cp16(sb + SM_A + b * A_ST + r * ROW_B + c * 16, src);
        }
        #pragma unroll
        for (int i = 0; i < 2; i++) {
            int idx = tid + 512 * i;
            int r   = idx >> 2;
            int c   = idx & 3;
            const char* src = wh + ((size_t)(bn + r) * K_TOTAL + k0 + c * 8) * 2;
            cp16(sb + SM_B + b * B_ST + r * ROW_B + c * 16, src);
        }
        asm volatile("cp.async.commit_group;");
    };

    // prologue: two stages in flight
    issue(0, 0);
    issue(1, 1);

    float acc[2][8][4];
    #pragma unroll
    for (int i = 0; i < 2; i++)
        #pragma unroll
        for (int j = 0; j < 8; j++)
            #pragma unroll
            for (int q = 0; q < 4; q++) acc[i][j][q] = 0.f;

    uint32_t aLane = (uint32_t)((warp_m * 32 + (lane & 15)) * ROW_B + ((lane >> 4) * 16));
    uint32_t bLane = (uint32_t)((warp_n * 64 + (lane & 7) + ((lane >> 4) << 3)) * ROW_B
                                + (((lane >> 3) & 1) * 16));

    const int NSTAGE = K_TOTAL / 32;   // 32
    #pragma unroll 1
    for (int s = 0; s < NSTAGE; s++) {
        // stage s must be complete; allow the later one(s) to stay in flight
        if (s + 1 < NSTAGE) asm volatile("cp.async.wait_group 1;" ::: "memory");
        else                asm volatile("cp.async.wait_group 0;" ::: "memory");
        __syncthreads();   // publish stage s to all warps; fences prior reads of buf (s+2)%3

        // prefetch stage s+2 into buffer (s+2)%3 == (s-1)%3 (read finished at iter s-1)
        if (s + 2 < NSTAGE) issue(s + 2, (s + 2) % 3);

        int b = s % 3;
        uint32_t aB = sb + SM_A + b * A_ST + aLane;
        uint32_t bB = sb + SM_B + b * B_ST + bLane;

        #pragma unroll
        for (int kk = 0; kk < 2; kk++) {
            uint32_t kb = kk * 32;
            uint32_t a[2][4], bf[4][4];
            #pragma unroll
            for (int mi = 0; mi < 2; mi++) ldsm4(a[mi], aB + kb + mi * 16 * ROW_B);
            #pragma unroll
            for (int bp = 0; bp < 4; bp++) ldsm4(bf[bp], bB + kb + bp * 16 * ROW_B);
            #pragma unroll
            for (int mi = 0; mi < 2; mi++)
                #pragma unroll
                for (int nj = 0; nj < 8; nj++)
                    mma_f16(acc[mi][nj], a[mi], &bf[nj >> 1][(nj & 1) * 2]);
        }
        // no trailing barrier: next iteration's sync (before its issue) protects buf reuse
    }

    // ---- epilogue: bias + relu + BN -> g_yh (fp16) ----
    const float* bs = (const float*)(smem + SM_PAR);
    const float* sc = bs + 256;
    const float* sh = bs + 512;
    __half* yh = (__half*)g_yh;
    #pragma unroll
    for (int mi = 0; mi < 2; mi++) {
        int m0 = bm + warp_m * 32 + mi * 16 + (lane >> 2);
        #pragma unroll
        for (int nj = 0; nj < 8; nj++) {
            int ln = warp_n * 64 + nj * 8 + (lane & 3) * 2;
            float s0 = sc[ln], s1 = sc[ln + 1];
            float h0 = sh[ln], h1 = sh[ln + 1];
            float b0 = bs[ln], b1 = bs[ln + 1];
            float z0 = fmaxf(acc[mi][nj][0] + b0, 0.f) * s0 + h0;
            float z1 = fmaxf(acc[mi][nj][1] + b1, 0.f) * s1 + h1;
            float z2 = fmaxf(acc[mi][nj][2] + b0, 0.f) * s0 + h0;
            float z3 = fmaxf(acc[mi][nj][3] + b1, 0.f) * s1 + h1;
            *(uint32_t*)(yh + (size_t)m0 * OUT_DIM + bn + ln)       = pack_h2(z0, z1);
            *(uint32_t*)(yh + (size_t)(m0 + 8) * OUT_DIM + bn + ln) = pack_h2(z2, z3);
        }
    }
}

// ---------------- row L2 normalize (fp16 in, fp32 out) ----------------
__global__ void k_normalize(float* __restrict__ out) {
    int row = blockIdx.x, t = threadIdx.x;      // 0..127, 4 halves each
    uint2 v = ((const uint2*)g_yh)[(size_t)row * 128 + t];
    float2 f0 = __half22float2(*(__half2*)&v.x);
    float2 f1 = __half22float2(*(__half2*)&v.y);
    float local = f0.x * f0.x + f0.y * f0.y + f1.x * f1.x + f1.y * f1.y;
    #pragma unroll
    for (int off = 16; off > 0; off >>= 1)
        local += __shfl_xor_sync(0xffffffffu, local, off);
    __shared__ float ws[4];
    int lane = t & 31, warp = t >> 5;
    if (lane == 0) ws[warp] = local;
    __syncthreads();
    float total = ws[0] + ws[1] + ws[2] + ws[3];
    float inv = 1.f / (sqrtf(total) + NORM_EPS);
    float4 o;
    o.x = f0.x * inv; o.y = f0.y * inv; o.z = f1.x * inv; o.w = f1.y * inv;
    ((float4*)(out + (size_t)row * OUT_DIM))[t] = o;
}

// ---------------- launch ----------------
extern "C" void kernel_launch(void* const* d_in, const int* in_sizes, int n_in,
                              void* d_out, int out_size)
{
    const float* feat  = (const float*)d_in[0];
    const void*  ei    = d_in[1];
    const float* W     = (const float*)d_in[2];
    const float* bias  = (const float*)d_in[3];
    const float* gamma = (const float*)d_in[4];
    const float* beta  = (const float*)d_in[5];
    const float* rmean = (const float*)d_in[6];
    const float* rvar  = (const float*)d_in[7];
    float*       out   = (float*)d_out;

    cudaFuncSetAttribute(k_gemm_mma, cudaFuncAttributeMaxDynamicSharedMemorySize, SMEM_BYTES);

    // CSR build (+dtype detect) and fp16 feature quantization
    k_zero_deg<<<N_NODES / 1024, 1024>>>((const int*)ei);
    k_quantF<<<(N_NODES * IN_DIM / 4) / 256, 256>>>(feat);
    k_hist<<<N_EDGES / 256, 256>>>(ei);
    k_scan_block<<<N_NODES / 1024, 1024>>>();
    k_scan_finish<<<N_NODES / 1024, 1024>>>();
    k_scatter_edges<<<N_EDGES / 256, 256>>>(ei);

    // gather aggregation from fp16 features
    k_aggregate<<<N_NODES, 128>>>();

    // quantize W to fp16
    k_quantW<<<(OUT_DIM * K_TOTAL / 4) / 256, 256>>>(W);

    // tensor-core GEMM + fused epilogue (y in fp16)
    dim3 ggrid(OUT_DIM / 256, N_NODES / 128);
    k_gemm_mma<<<ggrid, 512, SMEM_BYTES>>>(bias, gamma, beta, rmean, rvar);

    // row L2 normalize -> out
    k_normalize<<<N_NODES, 128>>>(out);
}

// round 15
// speedup vs baseline: 1.0662x; 1.0662x over previous
#include <cuda_runtime.h>
#include <cuda_fp16.h>
#include <math.h>
#include <stdint.h>

// ---------------- problem constants ----------------
#define N_NODES   65536
#define IN_DIM    512
#define OUT_DIM   512
#define N_EDGES   524288
#define K_TOTAL   (2 * IN_DIM)   // 1024
#define BN_EPS    1e-5f
#define NORM_EPS  1e-6f

// ---------------- device scratch ----------------
__device__ int    g_is64;
__device__ int    g_deg[N_NODES];
__device__ int    g_incl[N_NODES];
__device__ int    g_excl[N_NODES];
__device__ int    g_cursor[N_NODES];
__device__ int    g_blockSums[64];
__device__ int    g_tgtSorted[N_EDGES];
// X = concat(feat, agg) quantized to fp16: [node][1024] half (row = 128 uint4)
__device__ uint4  g_Xh[(size_t)N_NODES * K_TOTAL * 2 / 16];    // 128 MB
// W quantized to fp16: [512][1024] half
__device__ uint4  g_Wh[(size_t)OUT_DIM * K_TOTAL * 2 / 16];    // 1 MB
// pre-normalization activations, fp16: [node][512] half
__device__ uint4  g_yh[(size_t)N_NODES * OUT_DIM * 2 / 16];    // 64 MB

// ---------------- helpers ----------------
__device__ __forceinline__ uint32_t smem_u32(const void* p) {
    uint32_t a;
    asm("{ .reg .u64 t; cvta.to.shared.u64 t, %1; cvt.u32.u64 %0, t; }" : "=r"(a) : "l"(p));
    return a;
}
__device__ __forceinline__ uint2 quant4_h(float4 v) {
    __half2 p0, p1;
    p0.x = __float2half_rn(v.x); p0.y = __float2half_rn(v.y);
    p1.x = __float2half_rn(v.z); p1.y = __float2half_rn(v.w);
    return make_uint2(*(uint32_t*)&p0, *(uint32_t*)&p1);
}
__device__ __forceinline__ uint32_t pack_h2(float a, float b) {
    __half2 p;
    p.x = __float2half_rn(a); p.y = __float2half_rn(b);
    return *(uint32_t*)&p;
}
__device__ __forceinline__ void ldsm4(uint32_t* r, uint32_t addr) {
    asm volatile("ldmatrix.sync.aligned.m8n8.x4.shared.b16 {%0,%1,%2,%3}, [%4];"
                 : "=r"(r[0]), "=r"(r[1]), "=r"(r[2]), "=r"(r[3]) : "r"(addr));
}
__device__ __forceinline__ void mma_f16(float* d, const uint32_t* a, const uint32_t* b) {
    asm volatile("mma.sync.aligned.m16n8k16.row.col.f32.f16.f16.f32 "
                 "{%0,%1,%2,%3}, {%4,%5,%6,%7}, {%8,%9}, {%0,%1,%2,%3};"
                 : "+f"(d[0]), "+f"(d[1]), "+f"(d[2]), "+f"(d[3])
                 : "r"(a[0]), "r"(a[1]), "r"(a[2]), "r"(a[3]), "r"(b[0]), "r"(b[1]));
}
__device__ __forceinline__ void cp16(uint32_t dst, const void* src) {
    asm volatile("cp.async.cg.shared.global [%0], [%1], 16;" :: "r"(dst), "l"(src));
}

// ---------------- edge index dtype ----------------
__device__ __forceinline__ int load_edge(const void* ei, int idx) {
    if (g_is64) return (int)((const long long*)ei)[idx];
    return ((const int*)ei)[idx];
}

// ---------------- CSR build ----------------
__global__ void k_zero_deg(const int* __restrict__ ei32) {
    int i = blockIdx.x * blockDim.x + threadIdx.x;
    if (i < N_NODES) g_deg[i] = 0;
    if (i == 0) {
        int allzero = 1;
        for (int j = 0; j < 64; j++)
            if (ei32[2 * j + 1] != 0) { allzero = 0; break; }
        g_is64 = allzero;
    }
}
__global__ void k_hist(const void* __restrict__ ei) {
    int e = blockIdx.x * blockDim.x + threadIdx.x;
    if (e < N_EDGES) atomicAdd(&g_deg[load_edge(ei, e)], 1);
}
__global__ void k_scan_block() {
    __shared__ int s[1024];
    int t = threadIdx.x, gid = blockIdx.x * 1024 + t;
    s[t] = g_deg[gid];
    __syncthreads();
    #pragma unroll
    for (int off = 1; off < 1024; off <<= 1) {
        int v = (t >= off) ? s[t - off] : 0;
        __syncthreads();
        s[t] += v;
        __syncthreads();
    }
    g_incl[gid] = s[t];
    if (t == 1023) g_blockSums[blockIdx.x] = s[t];
}
// fused: per-block inline prefix of blockSums + finish
__global__ void k_scan_finish() {
    __shared__ int bsum[64];
    int t = threadIdx.x;
    if (t < 64) bsum[t] = g_blockSums[t];
    __syncthreads();
    int prefix = 0;
    #pragma unroll
    for (int j = 0; j < 64; j++)
        prefix += (j < blockIdx.x) ? bsum[j] : 0;
    int gid = blockIdx.x * 1024 + t;
    int excl = g_incl[gid] - g_deg[gid] + prefix;
    g_excl[gid] = excl;
    g_cursor[gid] = excl;
}
__global__ void k_scatter_edges(const void* __restrict__ ei) {
    int e = blockIdx.x * blockDim.x + threadIdx.x;
    if (e < N_EDGES) {
        int src = load_edge(ei, e);
        int tgt = load_edge(ei, N_EDGES + e);
        g_tgtSorted[atomicAdd(&g_cursor[src], 1)] = tgt;
    }
}

// ---------------- feat half of X -> fp16 ----------------
__global__ void k_quantF(const float* __restrict__ feat) {
    int idx = blockIdx.x * blockDim.x + threadIdx.x;   // one float4 each
    if (idx >= N_NODES * IN_DIM / 4) return;
    int node = idx >> 7;
    int c4   = idx & 127;
    float4 v = ((const float4*)feat)[idx];
    ((uint2*)g_Xh)[(size_t)node * 256 + c4] = quant4_h(v);
}

// ------- gather aggregation: 1 CTA = 2 nodes, 64 thr/node, uint4 loads ----
__global__ void k_aggregate() {
    int t  = threadIdx.x;                   // 0..127
    int g  = t >> 6;                        // node group 0/1
    int tt = t & 63;                        // uint4 chunk within row (16B = 8 halves)
    int node = blockIdx.x * 2 + g;
    int start = g_excl[node];
    int end   = start + g_deg[node];
    const uint4* xh = (const uint4*)g_Xh;   // row = 128 uint4; feat half = first 64

    float acc[8] = {0.f, 0.f, 0.f, 0.f, 0.f, 0.f, 0.f, 0.f};
    int e = start;
    for (; e + 1 < end; e += 2) {
        int t0 = g_tgtSorted[e];
        int t1 = g_tgtSorted[e + 1];
        uint4 v0 = __ldg(&xh[(size_t)t0 * 128 + tt]);
        uint4 v1 = __ldg(&xh[(size_t)t1 * 128 + tt]);
        float2 p;
        p = __half22float2(*(__half2*)&v0.x); acc[0] += p.x; acc[1] += p.y;
        p = __half22float2(*(__half2*)&v0.y); acc[2] += p.x; acc[3] += p.y;
        p = __half22float2(*(__half2*)&v0.z); acc[4] += p.x; acc[5] += p.y;
        p = __half22float2(*(__half2*)&v0.w); acc[6] += p.x; acc[7] += p.y;
        p = __half22float2(*(__half2*)&v1.x); acc[0] += p.x; acc[1] += p.y;
        p = __half22float2(*(__half2*)&v1.y); acc[2] += p.x; acc[3] += p.y;
        p = __half22float2(*(__half2*)&v1.z); acc[4] += p.x; acc[5] += p.y;
        p = __half22float2(*(__half2*)&v1.w); acc[6] += p.x; acc[7] += p.y;
    }
    if (e < end) {
        int t0 = g_tgtSorted[e];
        uint4 v0 = __ldg(&xh[(size_t)t0 * 128 + tt]);
        float2 p;
        p = __half22float2(*(__half2*)&v0.x); acc[0] += p.x; acc[1] += p.y;
        p = __half22float2(*(__half2*)&v0.y); acc[2] += p.x; acc[3] += p.y;
        p = __half22float2(*(__half2*)&v0.z); acc[4] += p.x; acc[5] += p.y;
        p = __half22float2(*(__half2*)&v0.w); acc[6] += p.x; acc[7] += p.y;
    }
    uint4 o;
    o.x = pack_h2(acc[0], acc[1]);
    o.y = pack_h2(acc[2], acc[3]);
    o.z = pack_h2(acc[4], acc[5]);
    o.w = pack_h2(acc[6], acc[7]);
    ((uint4*)g_Xh)[(size_t)node * 128 + 64 + tt] = o;
}

// ---------------- quantize W to fp16 ----------------
__global__ void k_quantW(const float* __restrict__ W) {
    int idx = blockIdx.x * blockDim.x + threadIdx.x;
    if (idx >= OUT_DIM * K_TOTAL / 4) return;
    float4 v = ((const float4*)W)[idx];
    ((uint2*)g_Wh)[idx] = quant4_h(v);
}

// ---------------- fp16 mma.sync GEMM: CTA 128(M) x 256(N), BK=32 ---------
// 512 threads, 16 warps; 2-stage cp.async double buffer (proven R13 config)
#define ROW_B   80                          // smem row stride bytes (32 fp16 + pad)
#define A_ST    (128 * ROW_B)               // 10240
#define B_ST    (256 * ROW_B)               // 20480
#define SM_PAR  0
#define SM_A    4096                        // 2 buf x A_ST
#define SM_B    (SM_A + 2 * A_ST)           // 24576; 2 buf x B_ST
#define SMEM_BYTES (SM_B + 2 * B_ST)        // 65536

__global__ void __launch_bounds__(512)
k_gemm_mma(const float* __restrict__ bias,
           const float* __restrict__ gamma,
           const float* __restrict__ beta,
           const float* __restrict__ rmean,
           const float* __restrict__ rvar)
{
    extern __shared__ char smem[];
    uint32_t sb = smem_u32(smem);
    int tid  = threadIdx.x;
    int wid  = tid >> 5;
    int lane = tid & 31;
    int warp_m = wid & 3;
    int warp_n = wid >> 2;
    int bm = blockIdx.y * 128;
    int bn = blockIdx.x * 256;

    if (tid < 256) {
        int n = bn + tid;
        float s = gamma[n] * rsqrtf(rvar[n] + BN_EPS);
        ((float*)(smem + SM_PAR))[tid]       = bias[n];
        ((float*)(smem + SM_PAR))[256 + tid] = s;
        ((float*)(smem + SM_PAR))[512 + tid] = beta[n] - rmean[n] * s;
    }

    const char* xh = (const char*)g_Xh;
    const char* wh = (const char*)g_Wh;

    auto issue = [&](int s, int b) {
        int k0 = s * 32;
        {
            int r = tid >> 2;
            int c = tid & 3;
            const char* src = xh + ((size_t)(bm + r) * K_TOTAL + k0 + c * 8) * 2;
            cp16(sb + SM_A + b * A_ST + r * ROW_B + c * 16, src);
        }
        #pragma unroll
        for (int i = 0; i < 2; i++) {
            int idx = tid + 512 * i;
            int r   = idx >> 2;
            int c   = idx & 3;
            const char* src = wh + ((size_t)(bn + r) * K_TOTAL + k0 + c * 8) * 2;
            cp16(sb + SM_B + b * B_ST + r * ROW_B + c * 16, src);
        }
        asm volatile("cp.async.commit_group;");
    };

    issue(0, 0);

    float acc[2][8][4];
    #pragma unroll
    for (int i = 0; i < 2; i++)
        #pragma unroll
        for (int j = 0; j < 8; j++)
            #pragma unroll
            for (int q = 0; q < 4; q++) acc[i][j][q] = 0.f;

    uint32_t aLane = (uint32_t)((warp_m * 32 + (lane & 15)) * ROW_B + ((lane >> 4) * 16));
    uint32_t bLane = (uint32_t)((warp_n * 64 + (lane & 7) + ((lane >> 4) << 3)) * ROW_B
                                + (((lane >> 3) & 1) * 16));

    const int NSTAGE = K_TOTAL / 32;   // 32
    #pragma unroll 1
    for (int s = 0; s < NSTAGE; s++) {
        int b = s & 1;
        if (s + 1 < NSTAGE) {
            issue(s + 1, (s + 1) & 1);
            asm volatile("cp.async.wait_group 1;" ::: "memory");
        } else {
            asm volatile("cp.async.wait_group 0;" ::: "memory");
        }
        __syncthreads();

        uint32_t aB = sb + SM_A + b * A_ST + aLane;
        uint32_t bB = sb + SM_B + b * B_ST + bLane;

        #pragma unroll
        for (int kk = 0; kk < 2; kk++) {
            uint32_t kb = kk * 32;
            uint32_t a[2][4], bf[4][4];
            #pragma unroll
            for (int mi = 0; mi < 2; mi++) ldsm4(a[mi], aB + kb + mi * 16 * ROW_B);
            #pragma unroll
            for (int bp = 0; bp < 4; bp++) ldsm4(bf[bp], bB + kb + bp * 16 * ROW_B);
            #pragma unroll
            for (int mi = 0; mi < 2; mi++)
                #pragma unroll
                for (int nj = 0; nj < 8; nj++)
                    mma_f16(acc[mi][nj], a[mi], &bf[nj >> 1][(nj & 1) * 2]);
        }
        __syncthreads();
    }

    // ---- epilogue: bias + relu + BN -> g_yh (fp16) ----
    const float* bs = (const float*)(smem + SM_PAR);
    const float* sc = bs + 256;
    const float* sh = bs + 512;
    __half* yh = (__half*)g_yh;
    #pragma unroll
    for (int mi = 0; mi < 2; mi++) {
        int m0 = bm + warp_m * 32 + mi * 16 + (lane >> 2);
        #pragma unroll
        for (int nj = 0; nj < 8; nj++) {
            int ln = warp_n * 64 + nj * 8 + (lane & 3) * 2;
            float s0 = sc[ln], s1 = sc[ln + 1];
            float h0 = sh[ln], h1 = sh[ln + 1];
            float b0 = bs[ln], b1 = bs[ln + 1];
            float z0 = fmaxf(acc[mi][nj][0] + b0, 0.f) * s0 + h0;
            float z1 = fmaxf(acc[mi][nj][1] + b1, 0.f) * s1 + h1;
            float z2 = fmaxf(acc[mi][nj][2] + b0, 0.f) * s0 + h0;
            float z3 = fmaxf(acc[mi][nj][3] + b1, 0.f) * s1 + h1;
            *(uint32_t*)(yh + (size_t)m0 * OUT_DIM + bn + ln)       = pack_h2(z0, z1);
            *(uint32_t*)(yh + (size_t)(m0 + 8) * OUT_DIM + bn + ln) = pack_h2(z2, z3);
        }
    }
}

// ---------------- row L2 normalize (fp16 in, fp32 out) ----------------
__global__ void k_normalize(float* __restrict__ out) {
    int row = blockIdx.x, t = threadIdx.x;      // 0..127, 4 halves each
    uint2 v = ((const uint2*)g_yh)[(size_t)row * 128 + t];
    float2 f0 = __half22float2(*(__half2*)&v.x);
    float2 f1 = __half22float2(*(__half2*)&v.y);
    float local = f0.x * f0.x + f0.y * f0.y + f1.x * f1.x + f1.y * f1.y;
    #pragma unroll
    for (int off = 16; off > 0; off >>= 1)
        local += __shfl_xor_sync(0xffffffffu, local, off);
    __shared__ float ws[4];
    int lane = t & 31, warp = t >> 5;
    if (lane == 0) ws[warp] = local;
    __syncthreads();
    float total = ws[0] + ws[1] + ws[2] + ws[3];
    float inv = 1.f / (sqrtf(total) + NORM_EPS);
    float4 o;
    o.x = f0.x * inv; o.y = f0.y * inv; o.z = f1.x * inv; o.w = f1.y * inv;
    ((float4*)(out + (size_t)row * OUT_DIM))[t] = o;
}

// ---------------- launch ----------------
extern "C" void kernel_launch(void* const* d_in, const int* in_sizes, int n_in,
                              void* d_out, int out_size)
{
    const float* feat  = (const float*)d_in[0];
    const void*  ei    = d_in[1];
    const float* W     = (const float*)d_in[2];
    const float* bias  = (const float*)d_in[3];
    const float* gamma = (const float*)d_in[4];
    const float* beta  = (const float*)d_in[5];
    const float* rmean = (const float*)d_in[6];
    const float* rvar  = (const float*)d_in[7];
    float*       out   = (float*)d_out;

    cudaFuncSetAttribute(k_gemm_mma, cudaFuncAttributeMaxDynamicSharedMemorySize, SMEM_BYTES);

    // CSR build (+dtype detect) and fp16 feature quantization
    k_zero_deg<<<N_NODES / 1024, 1024>>>((const int*)ei);
    k_quantF<<<(N_NODES * IN_DIM / 4) / 256, 256>>>(feat);
    k_hist<<<N_EDGES / 256, 256>>>(ei);
    k_scan_block<<<N_NODES / 1024, 1024>>>();
    k_scan_finish<<<N_NODES / 1024, 1024>>>();
    k_scatter_edges<<<N_EDGES / 256, 256>>>(ei);

    // gather aggregation from fp16 features (2 nodes per CTA, uint4 loads)
    k_aggregate<<<N_NODES / 2, 128>>>();

    // quantize W to fp16
    k_quantW<<<(OUT_DIM * K_TOTAL / 4) / 256, 256>>>(W);

    // tensor-core GEMM + fused epilogue (y in fp16)
    dim3 ggrid(OUT_DIM / 256, N_NODES / 128);
    k_gemm_mma<<<ggrid, 512, SMEM_BYTES>>>(bias, gamma, beta, rmean, rvar);

    // row L2 normalize -> out
    k_normalize<<<N_NODES, 128>>>(out);
}